// round 3
// baseline (speedup 1.0000x reference)
#include <cuda_runtime.h>
#include <cuda_bf16.h>
#include <math.h>

#define MAX_N 100000
#define MAX_E 1600000

// -------- scratch (static device globals; allocation-free) --------
static __device__ float g_bufA[(size_t)MAX_N * 128];
static __device__ float g_bufB[(size_t)MAX_N * 128];
static __device__ float g_dinv[MAX_N];
static __device__ int   g_indeg[MAX_N];
static __device__ int   g_cursor[MAX_N];
static __device__ int   g_offsets[MAX_N + 1];
static __device__ int   g_partials[1024];
static __device__ int   g_csr[MAX_E];
static __device__ float g_pool[128 * 64];
static __device__ int   g_cnt[128];

// -------- init / CSR build --------
__global__ void k_init(int n) {
    int stride = gridDim.x * blockDim.x;
    int i = blockIdx.x * blockDim.x + threadIdx.x;
    for (int j = i; j < n; j += stride) { g_indeg[j] = 0; g_cursor[j] = 0; }
    for (int j = i; j < 128 * 64; j += stride) g_pool[j] = 0.f;
    if (i < 128) g_cnt[i] = 0;
}

__global__ void k_count(const int* __restrict__ ei, int E) {
    int stride = gridDim.x * blockDim.x;
    for (int e = blockIdx.x * blockDim.x + threadIdx.x; e < E; e += stride) {
        int d = ei[E + e];
        atomicAdd(&g_indeg[d], 1);
    }
}

__global__ void k_dinv(int n) {
    int i = blockIdx.x * blockDim.x + threadIdx.x;
    if (i < n) g_dinv[i] = rsqrtf((float)(g_indeg[i] + 1));  // +1 self loop
}

// block-wise exclusive scan of g_indeg -> g_offsets, block totals -> g_partials
__global__ void k_scan1(int n) {
    __shared__ int s[256];
    int t = threadIdx.x;
    int idx = blockIdx.x * 256 + t;
    int v = (idx < n) ? g_indeg[idx] : 0;
    s[t] = v;
    __syncthreads();
    #pragma unroll
    for (int off = 1; off < 256; off <<= 1) {
        int add = (t >= off) ? s[t - off] : 0;
        __syncthreads();
        s[t] += add;
        __syncthreads();
    }
    if (idx < n) g_offsets[idx] = s[t] - v;        // exclusive
    if (t == 255) g_partials[blockIdx.x] = s[255]; // block total
}

__global__ void k_scan2(int nb) {
    __shared__ int s[512];
    int t = threadIdx.x;
    int v = (t < nb) ? g_partials[t] : 0;
    s[t] = v;
    __syncthreads();
    #pragma unroll
    for (int off = 1; off < 512; off <<= 1) {
        int add = (t >= off) ? s[t - off] : 0;
        __syncthreads();
        s[t] += add;
        __syncthreads();
    }
    if (t < nb) g_partials[t] = s[t] - v; // exclusive
}

__global__ void k_scan3(int n, int E) {
    int idx = blockIdx.x * 256 + threadIdx.x;
    if (idx < n) g_offsets[idx] += g_partials[blockIdx.x];
    if (idx == 0) g_offsets[n] = E;
}

__global__ void k_fill(const int* __restrict__ ei, int E) {
    int stride = gridDim.x * blockDim.x;
    for (int e = blockIdx.x * blockDim.x + threadIdx.x; e < E; e += stride) {
        int s = ei[e];
        int d = ei[E + e];
        int pos = g_offsets[d] + atomicAdd(&g_cursor[d], 1);
        g_csr[pos] = s;
    }
}

// -------- fused GEMM: out = epi(in @ W) ; epi options: +bias->tanh, *dinv[row] --------
template<int Fi, int Fo, bool TANHB, bool SCALE>
__global__ void __launch_bounds__(256) k_gemm(const float* __restrict__ in,
                                              const float* __restrict__ W,
                                              const float* __restrict__ bias,
                                              float* __restrict__ out, int n) {
    extern __shared__ float sW[];
    float* sB = sW + Fi * Fo;
    for (int i = threadIdx.x; i < Fi * Fo; i += 256) sW[i] = W[i];
    if (TANHB) for (int i = threadIdx.x; i < Fo; i += 256) sB[i] = bias[i];
    __syncthreads();

    constexpr int TPR = Fo / 4;       // threads per 4-row group (each does 4 cols)
    constexpr int GRP = 256 / TPR;    // groups per block
    const int grp = threadIdx.x / TPR;
    const int c4  = threadIdx.x % TPR;
    constexpr int RPB = GRP * 4;      // rows per block

    for (int row0 = blockIdx.x * RPB + grp * 4; row0 < n; row0 += gridDim.x * RPB) {
        float4 acc[4];
        #pragma unroll
        for (int r = 0; r < 4; r++) acc[r] = make_float4(0.f, 0.f, 0.f, 0.f);
        const int rmax = n - row0;  // >=1

        #pragma unroll 4
        for (int k = 0; k < Fi; k += 4) {
            float4 xr[4];
            #pragma unroll
            for (int r = 0; r < 4; r++)
                xr[r] = (r < rmax)
                    ? *reinterpret_cast<const float4*>(&in[(size_t)(row0 + r) * Fi + k])
                    : make_float4(0.f, 0.f, 0.f, 0.f);
            #pragma unroll
            for (int kk = 0; kk < 4; kk++) {
                float4 w = *reinterpret_cast<const float4*>(&sW[(k + kk) * Fo + 4 * c4]);
                #pragma unroll
                for (int r = 0; r < 4; r++) {
                    float xv = (kk == 0) ? xr[r].x : (kk == 1) ? xr[r].y : (kk == 2) ? xr[r].z : xr[r].w;
                    acc[r].x += xv * w.x; acc[r].y += xv * w.y;
                    acc[r].z += xv * w.z; acc[r].w += xv * w.w;
                }
            }
        }
        #pragma unroll
        for (int r = 0; r < 4; r++) {
            if (r < rmax) {
                int row = row0 + r;
                float4 a = acc[r];
                if (TANHB) {
                    float4 b4 = *reinterpret_cast<const float4*>(&sB[4 * c4]);
                    a.x = tanhf(a.x + b4.x); a.y = tanhf(a.y + b4.y);
                    a.z = tanhf(a.z + b4.z); a.w = tanhf(a.w + b4.w);
                }
                if (SCALE) {
                    float dv = g_dinv[row];
                    a.x *= dv; a.y *= dv; a.z *= dv; a.w *= dv;
                }
                *reinterpret_cast<float4*>(&out[(size_t)row * Fo + 4 * c4]) = a;
            }
        }
    }
}

// -------- aggregation over CSR (gather, no atomics) --------
// MODE 0: out = dinv[d] * (p[d] + sum p[src])               (pre-GEMM, aggregate-first)
// MODE 1: out = dinv[d] * tanh(dinv[d]*agg + b)             (post-GEMM, feeds next layer)
template<int F, int MODE>
__global__ void __launch_bounds__(256) k_agg(const float* __restrict__ p,
                                             const float* __restrict__ bias,
                                             float* __restrict__ out, int n) {
    constexpr int TPN = F / 4;
    int t = blockIdx.x * 256 + threadIdx.x;
    int d = t / TPN;
    int c4 = t % TPN;
    if (d >= n) return;

    const float4* p4 = reinterpret_cast<const float4*>(p);
    float4 a0 = p4[(size_t)d * TPN + c4];  // self loop (already dinv-scaled)
    float4 a1 = make_float4(0.f, 0.f, 0.f, 0.f);
    float4 a2 = make_float4(0.f, 0.f, 0.f, 0.f);
    float4 a3 = make_float4(0.f, 0.f, 0.f, 0.f);
    const int s0 = g_offsets[d], s1 = g_offsets[d + 1];
    int e = s0;
    // 4-wide unroll with independent accumulators: MLP_eff ~4 in the gather body
    for (; e + 4 <= s1; e += 4) {
        int i0 = g_csr[e], i1 = g_csr[e + 1], i2 = g_csr[e + 2], i3 = g_csr[e + 3];
        float4 v0 = __ldg(&p4[(size_t)i0 * TPN + c4]);
        float4 v1 = __ldg(&p4[(size_t)i1 * TPN + c4]);
        float4 v2 = __ldg(&p4[(size_t)i2 * TPN + c4]);
        float4 v3 = __ldg(&p4[(size_t)i3 * TPN + c4]);
        a0.x += v0.x; a0.y += v0.y; a0.z += v0.z; a0.w += v0.w;
        a1.x += v1.x; a1.y += v1.y; a1.z += v1.z; a1.w += v1.w;
        a2.x += v2.x; a2.y += v2.y; a2.z += v2.z; a2.w += v2.w;
        a3.x += v3.x; a3.y += v3.y; a3.z += v3.z; a3.w += v3.w;
    }
    for (; e < s1; e++) {
        int s = g_csr[e];
        float4 v = __ldg(&p4[(size_t)s * TPN + c4]);
        a0.x += v.x; a0.y += v.y; a0.z += v.z; a0.w += v.w;
    }
    float4 acc = make_float4(a0.x + a1.x + a2.x + a3.x,
                             a0.y + a1.y + a2.y + a3.y,
                             a0.z + a1.z + a2.z + a3.z,
                             a0.w + a1.w + a2.w + a3.w);
    float dv = g_dinv[d];
    float4 o;
    if (MODE == 0) {
        o = make_float4(dv * acc.x, dv * acc.y, dv * acc.z, dv * acc.w);
    } else {
        float4 b4 = *reinterpret_cast<const float4*>(&bias[4 * c4]);
        o.x = tanhf(dv * acc.x + b4.x);
        o.y = tanhf(dv * acc.y + b4.y);
        o.z = tanhf(dv * acc.z + b4.z);
        o.w = tanhf(dv * acc.w + b4.w);
        o.x *= dv; o.y *= dv; o.z *= dv; o.w *= dv;
    }
    reinterpret_cast<float4*>(out)[(size_t)d * TPN + c4] = o;
}

// -------- global mean pool (batch is sorted -> run-length + rare atomics) --------
__global__ void k_pool(const float* __restrict__ h, const int* __restrict__ batch, int n) {
    const int f = threadIdx.x; // 64 threads = 64 features
    int base = blockIdx.x * 512;
    int end = min(base + 512, n);
    float acc = 0.f; int cur = -1; int run = 0;
    for (int i = base; i < end; i++) {
        int g = batch[i];
        if (g != cur) {
            if (cur >= 0) {
                atomicAdd(&g_pool[cur * 64 + f], acc);
                if (f == 0) atomicAdd(&g_cnt[cur], run);
            }
            cur = g; acc = 0.f; run = 0;
        }
        acc += h[(size_t)i * 64 + f];
        run++;
    }
    if (cur >= 0) {
        atomicAdd(&g_pool[cur * 64 + f], acc);
        if (f == 0) atomicAdd(&g_cnt[cur], run);
    }
}

__global__ void k_final(const float* __restrict__ Wc, const float* __restrict__ bc,
                        float* __restrict__ out) {
    int warp = (blockIdx.x * blockDim.x + threadIdx.x) / 32;
    int lane = threadIdx.x & 31;
    if (warp >= 128) return;
    float c = fmaxf((float)g_cnt[warp], 1.f);
    float s = g_pool[warp * 64 + lane] * Wc[lane] + g_pool[warp * 64 + lane + 32] * Wc[lane + 32];
    #pragma unroll
    for (int off = 16; off; off >>= 1) s += __shfl_down_sync(0xffffffffu, s, off);
    if (lane == 0) out[warp] = s / c + bc[0];
}

// -------- host side --------
static float* symA() { static float* p = nullptr; if (!p) cudaGetSymbolAddress((void**)&p, g_bufA); return p; }
static float* symB() { static float* p = nullptr; if (!p) cudaGetSymbolAddress((void**)&p, g_bufB); return p; }

extern "C" void kernel_launch(void* const* d_in, const int* in_sizes, int n_in,
                              void* d_out, int out_size) {
    const float* x     = (const float*)d_in[0];
    const int*   ei    = (const int*)d_in[1];     // int32! (JAX x64 disabled)
    const int*   batch = (const int*)d_in[2];     // int32!
    const float* W1 = (const float*)d_in[3];  const float* b1 = (const float*)d_in[4];
    const float* W2 = (const float*)d_in[5];  const float* b2 = (const float*)d_in[6];
    const float* W3 = (const float*)d_in[7];  const float* b3 = (const float*)d_in[8];
    const float* W4 = (const float*)d_in[9];  const float* b4 = (const float*)d_in[10];
    const float* W5 = (const float*)d_in[11]; const float* b5 = (const float*)d_in[12];
    const float* Wc = (const float*)d_in[13]; const float* bc = (const float*)d_in[14];
    float* out = (float*)d_out;

    const int n = in_sizes[0] / 64;
    const int E = in_sizes[1] / 2;
    const int NB = (n + 255) / 256;

    float* A = symA();
    float* B = symB();

    // opt-in for 64KB+ dynamic smem on the 128x128 GEMM
    static bool attr_done = []() {
        cudaFuncSetAttribute((const void*)k_gemm<128,128,false,false>,
                             cudaFuncAttributeMaxDynamicSharedMemorySize,
                             (128 * 128 + 128) * 4);
        return true;
    }();
    (void)attr_done;

    // ---- CSR build ----
    k_init<<<512, 256>>>(n);
    k_count<<<(E + 255) / 256, 256>>>(ei, E);
    k_dinv<<<NB, 256>>>(n);
    k_scan1<<<NB, 256>>>(n);
    k_scan2<<<1, 512>>>(NB);
    k_scan3<<<NB, 256>>>(n, E);
    k_fill<<<(E + 255) / 256, 256>>>(ei, E);

    auto gblocks = [&](int Fo) { return (n * Fo / 4 + 255) / 256; }; // for agg
    auto gemmblk = [&](int Fo) { int rpb = 4096 / Fo; return (n + rpb - 1) / rpb; };

    // L1: 64->16, transform-first.  u = dinv * (x @ W1)
    k_gemm<64,16,false,true><<<gemmblk(16), 256, (64*16+16)*4>>>(x, W1, nullptr, A, n);
    k_agg<16,1><<<gblocks(16), 256>>>(A, b1, B, n);           // B = p1

    // L2: 16->128, aggregate-first.
    k_agg<16,0><<<gblocks(16), 256>>>(B, nullptr, A, n);      // A = v16
    k_gemm<16,128,true,true><<<gemmblk(128), 256, (16*128+128)*4>>>(A, W2, b2, B, n); // B = p2

    // L3: 128->128, transform-first.
    k_gemm<128,128,false,false><<<gemmblk(128), 256, (128*128+128)*4>>>(B, W3, nullptr, A, n);
    k_agg<128,1><<<gblocks(128), 256>>>(A, b3, B, n);         // B = p3

    // L4: 128->64, transform-first.
    k_gemm<128,64,false,false><<<gemmblk(64), 256, (128*64+64)*4>>>(B, W4, nullptr, A, n);
    k_agg<64,1><<<gblocks(64), 256>>>(A, b4, B, n);           // B = p4

    // L5: 64->64, aggregate-first; final output unscaled h5.
    k_agg<64,0><<<gblocks(64), 256>>>(B, nullptr, A, n);      // A = v64
    k_gemm<64,64,true,false><<<gemmblk(64), 256, (64*64+64)*4>>>(A, W5, b5, B, n);   // B = h5

    // ---- pool + head ----
    k_pool<<<(n + 511) / 512, 64>>>(B, batch, n);
    k_final<<<32, 128>>>(Wc, bc, out);
    (void)out_size; (void)n_in;
}

// round 5
// speedup vs baseline: 1.2807x; 1.2807x over previous
#include <cuda_runtime.h>
#include <cuda_fp16.h>
#include <math.h>

#define MAX_N 100000
#define MAX_E 1600000

// -------- scratch (static device globals; allocation-free) --------
static __device__ float g_bufA[(size_t)MAX_N * 128];
static __device__ float g_bufB[(size_t)MAX_N * 128];
static __device__ float g_dinv[MAX_N];
static __device__ int   g_indeg[MAX_N];
static __device__ int   g_cursor[MAX_N];
static __device__ int   g_offsets[MAX_N + 1];
static __device__ int   g_partials[1024];
static __device__ int   g_csr[MAX_E];
static __device__ float g_pool[128 * 64];
static __device__ int   g_cnt[128];

// -------- fp16 helpers --------
__device__ __forceinline__ void acc8(float* a, uint4 v) {
    __half2 h0 = *reinterpret_cast<__half2*>(&v.x);
    __half2 h1 = *reinterpret_cast<__half2*>(&v.y);
    __half2 h2 = *reinterpret_cast<__half2*>(&v.z);
    __half2 h3 = *reinterpret_cast<__half2*>(&v.w);
    float2 f0 = __half22float2(h0); a[0] += f0.x; a[1] += f0.y;
    float2 f1 = __half22float2(h1); a[2] += f1.x; a[3] += f1.y;
    float2 f2 = __half22float2(h2); a[4] += f2.x; a[5] += f2.y;
    float2 f3 = __half22float2(h3); a[6] += f3.x; a[7] += f3.y;
}

__device__ __forceinline__ uint4 pack8(const float* a) {
    __half2 h0 = __floats2half2_rn(a[0], a[1]);
    __half2 h1 = __floats2half2_rn(a[2], a[3]);
    __half2 h2 = __floats2half2_rn(a[4], a[5]);
    __half2 h3 = __floats2half2_rn(a[6], a[7]);
    uint4 r;
    r.x = *reinterpret_cast<unsigned*>(&h0);
    r.y = *reinterpret_cast<unsigned*>(&h1);
    r.z = *reinterpret_cast<unsigned*>(&h2);
    r.w = *reinterpret_cast<unsigned*>(&h3);
    return r;
}

// -------- init / CSR build --------
__global__ void k_init(int n) {
    int stride = gridDim.x * blockDim.x;
    int i = blockIdx.x * blockDim.x + threadIdx.x;
    for (int j = i; j < n; j += stride) { g_indeg[j] = 0; g_cursor[j] = 0; }
    for (int j = i; j < 128 * 64; j += stride) g_pool[j] = 0.f;
    if (i < 128) g_cnt[i] = 0;
}

__global__ void k_count(const int* __restrict__ ei, int E) {
    int stride = gridDim.x * blockDim.x;
    for (int e = blockIdx.x * blockDim.x + threadIdx.x; e < E; e += stride) {
        int d = ei[E + e];
        atomicAdd(&g_indeg[d], 1);
    }
}

// block-wise exclusive scan of g_indeg -> g_offsets (+ fused dinv)
__global__ void k_scan1(int n) {
    __shared__ int s[256];
    int t = threadIdx.x;
    int idx = blockIdx.x * 256 + t;
    int v = (idx < n) ? g_indeg[idx] : 0;
    if (idx < n) g_dinv[idx] = rsqrtf((float)(v + 1));  // +1 self loop
    s[t] = v;
    __syncthreads();
    #pragma unroll
    for (int off = 1; off < 256; off <<= 1) {
        int add = (t >= off) ? s[t - off] : 0;
        __syncthreads();
        s[t] += add;
        __syncthreads();
    }
    if (idx < n) g_offsets[idx] = s[t] - v;        // exclusive
    if (t == 255) g_partials[blockIdx.x] = s[255]; // block total
}

__global__ void k_scan2(int nb) {
    __shared__ int s[512];
    int t = threadIdx.x;
    int v = (t < nb) ? g_partials[t] : 0;
    s[t] = v;
    __syncthreads();
    #pragma unroll
    for (int off = 1; off < 512; off <<= 1) {
        int add = (t >= off) ? s[t - off] : 0;
        __syncthreads();
        s[t] += add;
        __syncthreads();
    }
    if (t < nb) g_partials[t] = s[t] - v; // exclusive
}

__global__ void k_scan3(int n, int E) {
    int idx = blockIdx.x * 256 + threadIdx.x;
    if (idx < n) g_offsets[idx] += g_partials[blockIdx.x];
    if (idx == 0) g_offsets[n] = E;
}

__global__ void k_fill(const int* __restrict__ ei, int E) {
    int stride = gridDim.x * blockDim.x;
    for (int e = blockIdx.x * blockDim.x + threadIdx.x; e < E; e += stride) {
        int s = ei[e];
        int d = ei[E + e];
        int pos = g_offsets[d] + atomicAdd(&g_cursor[d], 1);
        g_csr[pos] = s;
    }
}

// -------- fused GEMM: out = epi(in @ W); in fp32, out fp32 or fp16 --------
template<int Fi, int Fo, bool TANHB, bool SCALE, bool OUTH>
__global__ void __launch_bounds__(256) k_gemm(const float* __restrict__ in,
                                              const float* __restrict__ W,
                                              const float* __restrict__ bias,
                                              void* __restrict__ outv, int n) {
    extern __shared__ float sW[];
    float* sB = sW + Fi * Fo;
    for (int i = threadIdx.x; i < Fi * Fo; i += 256) sW[i] = W[i];
    if (TANHB) for (int i = threadIdx.x; i < Fo; i += 256) sB[i] = bias[i];
    __syncthreads();

    constexpr int TPR = Fo / 4;       // threads per 4-row group (each does 4 cols)
    constexpr int GRP = 256 / TPR;    // groups per block
    const int grp = threadIdx.x / TPR;
    const int c4  = threadIdx.x % TPR;
    constexpr int RPB = GRP * 4;      // rows per block

    for (int row0 = blockIdx.x * RPB + grp * 4; row0 < n; row0 += gridDim.x * RPB) {
        float4 acc[4];
        #pragma unroll
        for (int r = 0; r < 4; r++) acc[r] = make_float4(0.f, 0.f, 0.f, 0.f);
        const int rmax = n - row0;  // >=1

        #pragma unroll 4
        for (int k = 0; k < Fi; k += 4) {
            float4 xr[4];
            #pragma unroll
            for (int r = 0; r < 4; r++)
                xr[r] = (r < rmax)
                    ? *reinterpret_cast<const float4*>(&in[(size_t)(row0 + r) * Fi + k])
                    : make_float4(0.f, 0.f, 0.f, 0.f);
            #pragma unroll
            for (int kk = 0; kk < 4; kk++) {
                float4 w = *reinterpret_cast<const float4*>(&sW[(k + kk) * Fo + 4 * c4]);
                #pragma unroll
                for (int r = 0; r < 4; r++) {
                    float xv = (kk == 0) ? xr[r].x : (kk == 1) ? xr[r].y : (kk == 2) ? xr[r].z : xr[r].w;
                    acc[r].x += xv * w.x; acc[r].y += xv * w.y;
                    acc[r].z += xv * w.z; acc[r].w += xv * w.w;
                }
            }
        }
        #pragma unroll
        for (int r = 0; r < 4; r++) {
            if (r < rmax) {
                int row = row0 + r;
                float4 a = acc[r];
                if (TANHB) {
                    float4 b4 = *reinterpret_cast<const float4*>(&sB[4 * c4]);
                    a.x = tanhf(a.x + b4.x); a.y = tanhf(a.y + b4.y);
                    a.z = tanhf(a.z + b4.z); a.w = tanhf(a.w + b4.w);
                }
                if (SCALE) {
                    float dv = g_dinv[row];
                    a.x *= dv; a.y *= dv; a.z *= dv; a.w *= dv;
                }
                if (OUTH) {
                    __half2 h0 = __floats2half2_rn(a.x, a.y);
                    __half2 h1 = __floats2half2_rn(a.z, a.w);
                    uint2 u; u.x = *reinterpret_cast<unsigned*>(&h0);
                    u.y = *reinterpret_cast<unsigned*>(&h1);
                    *reinterpret_cast<uint2*>((__half*)outv + (size_t)row * Fo + 4 * c4) = u;
                } else {
                    *reinterpret_cast<float4*>((float*)outv + (size_t)row * Fo + 4 * c4) = a;
                }
            }
        }
    }
}

// -------- aggregation over CSR (gather, no atomics); input table is fp16 --------
// MODE 0: out = dinv[d] * (p[d] + sum p[src])               (pre-GEMM, aggregate-first)
// MODE 1: out = dinv[d] * tanh(dinv[d]*agg + b)             (post-GEMM, feeds next layer)
template<int F, int MODE, bool OUTH>
__global__ void __launch_bounds__(256) k_agg(const __half* __restrict__ p,
                                             const float* __restrict__ bias,
                                             void* __restrict__ outv, int n) {
    constexpr int TPN = F / 8;  // each thread covers 8 features (16B fp16)
    int t = blockIdx.x * 256 + threadIdx.x;
    int d = t / TPN;
    int c8 = t % TPN;
    if (d >= n) return;

    const uint4* p4 = reinterpret_cast<const uint4*>(p);  // row stride TPN uint4
    float a0[8], a1[8];
    #pragma unroll
    for (int j = 0; j < 8; j++) { a0[j] = 0.f; a1[j] = 0.f; }
    acc8(a0, p4[(size_t)d * TPN + c8]);  // self loop (already dinv-scaled)

    const int s0 = g_offsets[d], s1 = g_offsets[d + 1];
    int e = s0;
    // 4-wide unroll: 4 independent gathers in flight (MLP ~4)
    for (; e + 4 <= s1; e += 4) {
        int i0 = g_csr[e], i1 = g_csr[e + 1], i2 = g_csr[e + 2], i3 = g_csr[e + 3];
        uint4 v0 = __ldg(&p4[(size_t)i0 * TPN + c8]);
        uint4 v1 = __ldg(&p4[(size_t)i1 * TPN + c8]);
        uint4 v2 = __ldg(&p4[(size_t)i2 * TPN + c8]);
        uint4 v3 = __ldg(&p4[(size_t)i3 * TPN + c8]);
        acc8(a0, v0); acc8(a1, v1); acc8(a0, v2); acc8(a1, v3);
    }
    for (; e < s1; e++) {
        uint4 v = __ldg(&p4[(size_t)g_csr[e] * TPN + c8]);
        acc8(a0, v);
    }
    float dv = g_dinv[d];
    float o[8];
    if (MODE == 0) {
        #pragma unroll
        for (int j = 0; j < 8; j++) o[j] = dv * (a0[j] + a1[j]);
    } else {
        const float* b = &bias[c8 * 8];
        #pragma unroll
        for (int j = 0; j < 8; j++) o[j] = dv * tanhf(dv * (a0[j] + a1[j]) + b[j]);
    }
    if (OUTH) {
        *reinterpret_cast<uint4*>((__half*)outv + (size_t)d * F + c8 * 8) = pack8(o);
    } else {
        float* op = (float*)outv + (size_t)d * F + c8 * 8;
        *reinterpret_cast<float4*>(op)     = make_float4(o[0], o[1], o[2], o[3]);
        *reinterpret_cast<float4*>(op + 4) = make_float4(o[4], o[5], o[6], o[7]);
    }
}

// -------- global mean pool: thread per (row, float4), direct atomics + warp merge --------
__global__ void __launch_bounds__(256) k_pool(const float* __restrict__ h,
                                              const int* __restrict__ batch, int n) {
    int idx = blockIdx.x * 256 + threadIdx.x;
    int row = idx >> 4;
    int c4 = idx & 15;
    if (row >= n) return;
    int g = batch[row];
    float4 v = reinterpret_cast<const float4*>(h)[(size_t)row * 16 + c4];

    // warp merge: lane l (<16, row r) pairs with lane l+16 (row r+1)
    unsigned m = 0xffffffffu;
    int lane = threadIdx.x & 31;
    int g_dn = __shfl_down_sync(m, g, 16);
    float4 w;
    w.x = __shfl_down_sync(m, v.x, 16); w.y = __shfl_down_sync(m, v.y, 16);
    w.z = __shfl_down_sync(m, v.z, 16); w.w = __shfl_down_sync(m, v.w, 16);
    int g_up = __shfl_up_sync(m, g, 16);
    bool do_atomic;
    if (lane < 16) {
        bool partner_valid = (row + 1 < n) && (g_dn == g);
        if (partner_valid) { v.x += w.x; v.y += w.y; v.z += w.z; v.w += w.w; }
        do_atomic = true;
    } else {
        do_atomic = (g_up != g);  // not absorbed by partner
    }
    if (do_atomic) {
        float* dst = &g_pool[g * 64 + c4 * 4];
        atomicAdd(dst + 0, v.x); atomicAdd(dst + 1, v.y);
        atomicAdd(dst + 2, v.z); atomicAdd(dst + 3, v.w);
        if (c4 == 0) {
            int cnt = (lane < 16 && (row + 1 < n) && (g_dn == g)) ? 2 : 1;
            atomicAdd(&g_cnt[g], cnt);
        }
    }
}

__global__ void k_final(const float* __restrict__ Wc, const float* __restrict__ bc,
                        float* __restrict__ out) {
    int warp = (blockIdx.x * blockDim.x + threadIdx.x) / 32;
    int lane = threadIdx.x & 31;
    if (warp >= 128) return;
    float c = fmaxf((float)g_cnt[warp], 1.f);
    float s = g_pool[warp * 64 + lane] * Wc[lane] + g_pool[warp * 64 + lane + 32] * Wc[lane + 32];
    #pragma unroll
    for (int off = 16; off; off >>= 1) s += __shfl_down_sync(0xffffffffu, s, off);
    if (lane == 0) out[warp] = s / c + bc[0];
}

// -------- host side --------
static float* symA() { static float* p = nullptr; if (!p) cudaGetSymbolAddress((void**)&p, g_bufA); return p; }
static float* symB() { static float* p = nullptr; if (!p) cudaGetSymbolAddress((void**)&p, g_bufB); return p; }

extern "C" void kernel_launch(void* const* d_in, const int* in_sizes, int n_in,
                              void* d_out, int out_size) {
    const float* x     = (const float*)d_in[0];
    const int*   ei    = (const int*)d_in[1];     // int32 (JAX x64 disabled)
    const int*   batch = (const int*)d_in[2];     // int32
    const float* W1 = (const float*)d_in[3];  const float* b1 = (const float*)d_in[4];
    const float* W2 = (const float*)d_in[5];  const float* b2 = (const float*)d_in[6];
    const float* W3 = (const float*)d_in[7];  const float* b3 = (const float*)d_in[8];
    const float* W4 = (const float*)d_in[9];  const float* b4 = (const float*)d_in[10];
    const float* W5 = (const float*)d_in[11]; const float* b5 = (const float*)d_in[12];
    const float* Wc = (const float*)d_in[13]; const float* bc = (const float*)d_in[14];
    float* out = (float*)d_out;

    const int n = in_sizes[0] / 64;
    const int E = in_sizes[1] / 2;
    const int NB = (n + 255) / 256;

    float* A = symA();
    float* B = symB();
    __half* Ah = (__half*)A;
    __half* Bh = (__half*)B;

    // opt-in for 64KB+ dynamic smem on the 128x128 GEMM
    static bool attr_done = []() {
        cudaFuncSetAttribute((const void*)k_gemm<128,128,false,false,true>,
                             cudaFuncAttributeMaxDynamicSharedMemorySize,
                             (128 * 128 + 128) * 4);
        return true;
    }();
    (void)attr_done;

    // ---- CSR build ----
    k_init<<<512, 256>>>(n);
    k_count<<<(E + 255) / 256, 256>>>(ei, E);
    k_scan1<<<NB, 256>>>(n);
    k_scan2<<<1, 512>>>(NB);
    k_scan3<<<NB, 256>>>(n, E);
    k_fill<<<(E + 255) / 256, 256>>>(ei, E);

    auto ablocks = [&](int F) { return (n * (F / 8) + 255) / 256; };   // agg grids
    auto gemmblk = [&](int Fo) { int rpb = 4096 / Fo; return (n + rpb - 1) / rpb; };

    // L1: 64->16, transform-first.  Ah = fp16( dinv * (x @ W1) )
    k_gemm<64,16,false,true,true><<<gemmblk(16), 256, (64*16+16)*4>>>(x, W1, nullptr, Ah, n);
    k_agg<16,1,true><<<ablocks(16), 256>>>(Ah, b1, Bh, n);          // Bh = p1 (fp16)

    // L2: 16->128, aggregate-first.
    k_agg<16,0,false><<<ablocks(16), 256>>>(Bh, nullptr, A, n);     // A = v16 (fp32)
    k_gemm<16,128,true,true,false><<<gemmblk(128), 256, (16*128+128)*4>>>(A, W2, b2, B, n); // B = p2 fp32

    // L3: 128->128, transform-first.
    k_gemm<128,128,false,false,true><<<gemmblk(128), 256, (128*128+128)*4>>>(B, W3, nullptr, Ah, n);
    k_agg<128,1,false><<<ablocks(128), 256>>>(Ah, b3, B, n);        // B = p3 (fp32)

    // L4: 128->64, transform-first.
    k_gemm<128,64,false,false,true><<<gemmblk(64), 256, (128*64+64)*4>>>(B, W4, nullptr, Ah, n);
    k_agg<64,1,true><<<ablocks(64), 256>>>(Ah, b4, Bh, n);          // Bh = p4 (fp16)

    // L5: 64->64, aggregate-first; final output fp32 h5.
    k_agg<64,0,false><<<ablocks(64), 256>>>(Bh, nullptr, A, n);     // A = v64 (fp32)
    k_gemm<64,64,true,false,false><<<gemmblk(64), 256, (64*64+64)*4>>>(A, W5, b5, B, n);   // B = h5 fp32

    // ---- pool + head ----
    k_pool<<<(n * 16 + 255) / 256, 256>>>(B, batch, n);
    k_final<<<32, 128>>>(Wc, bc, out);
    (void)out_size; (void)n_in;
}

// round 6
// speedup vs baseline: 1.3813x; 1.0786x over previous
#include <cuda_runtime.h>
#include <cuda_fp16.h>
#include <math.h>

#define MAX_N 100000
#define MAX_E 1600000

// -------- scratch (static device globals; allocation-free) --------
static __device__ float g_bufA[(size_t)MAX_N * 128];
static __device__ float g_bufB[(size_t)MAX_N * 128];
static __device__ float g_dinv[MAX_N];
static __device__ int   g_indeg[MAX_N];
static __device__ int   g_cursor[MAX_N];
static __device__ int   g_offsets[MAX_N + 1];
static __device__ int   g_partials[1024];
static __device__ int   g_csr[MAX_E];
static __device__ float g_pool[128 * 64];
static __device__ int   g_cnt[128];

// -------- fp16 helpers --------
__device__ __forceinline__ void acc8(float* a, uint4 v) {
    __half2 h0 = *reinterpret_cast<__half2*>(&v.x);
    __half2 h1 = *reinterpret_cast<__half2*>(&v.y);
    __half2 h2 = *reinterpret_cast<__half2*>(&v.z);
    __half2 h3 = *reinterpret_cast<__half2*>(&v.w);
    float2 f0 = __half22float2(h0); a[0] += f0.x; a[1] += f0.y;
    float2 f1 = __half22float2(h1); a[2] += f1.x; a[3] += f1.y;
    float2 f2 = __half22float2(h2); a[4] += f2.x; a[5] += f2.y;
    float2 f3 = __half22float2(h3); a[6] += f3.x; a[7] += f3.y;
}

__device__ __forceinline__ void cvt8(float* a, uint4 v) {
    __half2 h0 = *reinterpret_cast<__half2*>(&v.x);
    __half2 h1 = *reinterpret_cast<__half2*>(&v.y);
    __half2 h2 = *reinterpret_cast<__half2*>(&v.z);
    __half2 h3 = *reinterpret_cast<__half2*>(&v.w);
    float2 f0 = __half22float2(h0); a[0] = f0.x; a[1] = f0.y;
    float2 f1 = __half22float2(h1); a[2] = f1.x; a[3] = f1.y;
    float2 f2 = __half22float2(h2); a[4] = f2.x; a[5] = f2.y;
    float2 f3 = __half22float2(h3); a[6] = f3.x; a[7] = f3.y;
}

__device__ __forceinline__ uint4 pack8(const float* a) {
    __half2 h0 = __floats2half2_rn(a[0], a[1]);
    __half2 h1 = __floats2half2_rn(a[2], a[3]);
    __half2 h2 = __floats2half2_rn(a[4], a[5]);
    __half2 h3 = __floats2half2_rn(a[6], a[7]);
    uint4 r;
    r.x = *reinterpret_cast<unsigned*>(&h0);
    r.y = *reinterpret_cast<unsigned*>(&h1);
    r.z = *reinterpret_cast<unsigned*>(&h2);
    r.w = *reinterpret_cast<unsigned*>(&h3);
    return r;
}

// gather 8 features (uint4 of fp16) for node d, lane-chunk c8; o = self + sum(neighbors)
template<int TPN>
__device__ __forceinline__ void gather8(const uint4* __restrict__ p4, int d, int c8, float* o) {
    float a0[8], a1[8];
    #pragma unroll
    for (int j = 0; j < 8; j++) { a0[j] = 0.f; a1[j] = 0.f; }
    acc8(a0, p4[(size_t)d * TPN + c8]);  // self loop
    const int s0 = g_offsets[d], s1 = g_offsets[d + 1];
    int e = s0;
    for (; e + 4 <= s1; e += 4) {
        int i0 = g_csr[e], i1 = g_csr[e + 1], i2 = g_csr[e + 2], i3 = g_csr[e + 3];
        uint4 v0 = __ldg(&p4[(size_t)i0 * TPN + c8]);
        uint4 v1 = __ldg(&p4[(size_t)i1 * TPN + c8]);
        uint4 v2 = __ldg(&p4[(size_t)i2 * TPN + c8]);
        uint4 v3 = __ldg(&p4[(size_t)i3 * TPN + c8]);
        acc8(a0, v0); acc8(a1, v1); acc8(a0, v2); acc8(a1, v3);
    }
    for (; e < s1; e++) {
        uint4 v = __ldg(&p4[(size_t)g_csr[e] * TPN + c8]);
        acc8(a0, v);
    }
    #pragma unroll
    for (int j = 0; j < 8; j++) o[j] = a0[j] + a1[j];
}

// -------- init / CSR build --------
__global__ void k_init(int n) {
    int stride = gridDim.x * blockDim.x;
    int i = blockIdx.x * blockDim.x + threadIdx.x;
    for (int j = i; j < n; j += stride) { g_indeg[j] = 0; g_cursor[j] = 0; }
    for (int j = i; j < 128 * 64; j += stride) g_pool[j] = 0.f;
    if (i < 128) g_cnt[i] = 0;
}

__global__ void k_count(const int* __restrict__ ei, int E) {
    int stride = gridDim.x * blockDim.x;
    for (int e = blockIdx.x * blockDim.x + threadIdx.x; e < E; e += stride) {
        int d = ei[E + e];
        atomicAdd(&g_indeg[d], 1);
    }
}

// block-wise exclusive scan of g_indeg -> g_offsets (+ fused dinv)
__global__ void k_scan1(int n) {
    __shared__ int s[256];
    int t = threadIdx.x;
    int idx = blockIdx.x * 256 + t;
    int v = (idx < n) ? g_indeg[idx] : 0;
    if (idx < n) g_dinv[idx] = rsqrtf((float)(v + 1));  // +1 self loop
    s[t] = v;
    __syncthreads();
    #pragma unroll
    for (int off = 1; off < 256; off <<= 1) {
        int add = (t >= off) ? s[t - off] : 0;
        __syncthreads();
        s[t] += add;
        __syncthreads();
    }
    if (idx < n) g_offsets[idx] = s[t] - v;        // exclusive
    if (t == 255) g_partials[blockIdx.x] = s[255]; // block total
}

__global__ void k_scan2(int nb) {
    __shared__ int s[512];
    int t = threadIdx.x;
    int v = (t < nb) ? g_partials[t] : 0;
    s[t] = v;
    __syncthreads();
    #pragma unroll
    for (int off = 1; off < 512; off <<= 1) {
        int add = (t >= off) ? s[t - off] : 0;
        __syncthreads();
        s[t] += add;
        __syncthreads();
    }
    if (t < nb) g_partials[t] = s[t] - v; // exclusive
}

__global__ void k_scan3(int n, int E) {
    int idx = blockIdx.x * 256 + threadIdx.x;
    if (idx < n) g_offsets[idx] += g_partials[blockIdx.x];
    if (idx == 0) g_offsets[n] = E;
}

__global__ void k_fill(const int* __restrict__ ei, int E) {
    int stride = gridDim.x * blockDim.x;
    for (int e = blockIdx.x * blockDim.x + threadIdx.x; e < E; e += stride) {
        int s = ei[e];
        int d = ei[E + e];
        int pos = g_offsets[d] + atomicAdd(&g_cursor[d], 1);
        g_csr[pos] = s;
    }
}

// -------- fused GEMM: out = epi(in @ W); in fp32 or fp16, out fp32 or fp16 --------
template<int Fi, int Fo, bool TANHB, bool SCALE, bool OUTH, bool INH>
__global__ void __launch_bounds__(256) k_gemm(const void* __restrict__ inv,
                                              const float* __restrict__ W,
                                              const float* __restrict__ bias,
                                              void* __restrict__ outv, int n) {
    extern __shared__ float sW[];
    float* sB = sW + Fi * Fo;
    for (int i = threadIdx.x; i < Fi * Fo; i += 256) sW[i] = W[i];
    if (TANHB) for (int i = threadIdx.x; i < Fo; i += 256) sB[i] = bias[i];
    __syncthreads();

    constexpr int TPR = Fo / 4;       // threads per 4-row group (each does 4 cols)
    constexpr int GRP = 256 / TPR;    // groups per block
    const int grp = threadIdx.x / TPR;
    const int c4  = threadIdx.x % TPR;
    constexpr int RPB = GRP * 4;      // rows per block

    for (int row0 = blockIdx.x * RPB + grp * 4; row0 < n; row0 += gridDim.x * RPB) {
        float4 acc[4];
        #pragma unroll
        for (int r = 0; r < 4; r++) acc[r] = make_float4(0.f, 0.f, 0.f, 0.f);
        const int rmax = n - row0;  // >=1

        if (INH) {
            const uint4* in8 = reinterpret_cast<const uint4*>(inv);  // fp16, 8/chunk
            #pragma unroll 2
            for (int k = 0; k < Fi; k += 8) {
                float xf[4][8];
                #pragma unroll
                for (int r = 0; r < 4; r++) {
                    if (r < rmax) {
                        uint4 v = in8[(size_t)(row0 + r) * (Fi / 8) + k / 8];
                        cvt8(xf[r], v);
                    } else {
                        #pragma unroll
                        for (int j = 0; j < 8; j++) xf[r][j] = 0.f;
                    }
                }
                #pragma unroll
                for (int kk = 0; kk < 8; kk++) {
                    float4 w = *reinterpret_cast<const float4*>(&sW[(k + kk) * Fo + 4 * c4]);
                    #pragma unroll
                    for (int r = 0; r < 4; r++) {
                        float xv = xf[r][kk];
                        acc[r].x += xv * w.x; acc[r].y += xv * w.y;
                        acc[r].z += xv * w.z; acc[r].w += xv * w.w;
                    }
                }
            }
        } else {
            const float* in = reinterpret_cast<const float*>(inv);
            #pragma unroll 4
            for (int k = 0; k < Fi; k += 4) {
                float4 xr[4];
                #pragma unroll
                for (int r = 0; r < 4; r++)
                    xr[r] = (r < rmax)
                        ? *reinterpret_cast<const float4*>(&in[(size_t)(row0 + r) * Fi + k])
                        : make_float4(0.f, 0.f, 0.f, 0.f);
                #pragma unroll
                for (int kk = 0; kk < 4; kk++) {
                    float4 w = *reinterpret_cast<const float4*>(&sW[(k + kk) * Fo + 4 * c4]);
                    #pragma unroll
                    for (int r = 0; r < 4; r++) {
                        float xv = (kk == 0) ? xr[r].x : (kk == 1) ? xr[r].y : (kk == 2) ? xr[r].z : xr[r].w;
                        acc[r].x += xv * w.x; acc[r].y += xv * w.y;
                        acc[r].z += xv * w.z; acc[r].w += xv * w.w;
                    }
                }
            }
        }
        #pragma unroll
        for (int r = 0; r < 4; r++) {
            if (r < rmax) {
                int row = row0 + r;
                float4 a = acc[r];
                if (TANHB) {
                    float4 b4 = *reinterpret_cast<const float4*>(&sB[4 * c4]);
                    a.x = tanhf(a.x + b4.x); a.y = tanhf(a.y + b4.y);
                    a.z = tanhf(a.z + b4.z); a.w = tanhf(a.w + b4.w);
                }
                if (SCALE) {
                    float dv = g_dinv[row];
                    a.x *= dv; a.y *= dv; a.z *= dv; a.w *= dv;
                }
                if (OUTH) {
                    __half2 h0 = __floats2half2_rn(a.x, a.y);
                    __half2 h1 = __floats2half2_rn(a.z, a.w);
                    uint2 u; u.x = *reinterpret_cast<unsigned*>(&h0);
                    u.y = *reinterpret_cast<unsigned*>(&h1);
                    *reinterpret_cast<uint2*>((__half*)outv + (size_t)row * Fo + 4 * c4) = u;
                } else {
                    *reinterpret_cast<float4*>((float*)outv + (size_t)row * Fo + 4 * c4) = a;
                }
            }
        }
    }
}

// -------- standalone aggregation (post-GEMM, MODE1): out = dinv*tanh(dinv*agg+b), fp16 out --------
template<int F>
__global__ void __launch_bounds__(256) k_agg1(const __half* __restrict__ p,
                                              const float* __restrict__ bias,
                                              __half* __restrict__ outh, int n) {
    constexpr int TPN = F / 8;
    int t = blockIdx.x * 256 + threadIdx.x;
    int d = t / TPN;
    int c8 = t % TPN;
    if (d >= n) return;
    float s[8];
    gather8<TPN>(reinterpret_cast<const uint4*>(p), d, c8, s);
    float dv = g_dinv[d];
    const float* b = &bias[c8 * 8];
    float o[8];
    #pragma unroll
    for (int j = 0; j < 8; j++) o[j] = dv * tanhf(dv * s[j] + b[j]);
    *reinterpret_cast<uint4*>(outh + (size_t)d * F + c8 * 8) = pack8(o);
}

// -------- L2 fused: v16 = dinv*(agg p1) in smem -> GEMM 16->128 -> tanh,dinv -> fp16 --------
__global__ void __launch_bounds__(256) k_l2fused(const __half* __restrict__ p1,
                                                 const float* __restrict__ W2,
                                                 const float* __restrict__ b2,
                                                 __half* __restrict__ outh, int n) {
    __shared__ float sV[128][16];
    __shared__ float sW[16 * 128];
    __shared__ float sB[128];
    int t = threadIdx.x;
    for (int i = t; i < 16 * 128; i += 256) sW[i] = W2[i];
    if (t < 128) sB[t] = b2[t];
    int base = blockIdx.x * 128;
    // phase A: 2 threads per row, 128 rows
    {
        int r = t >> 1, c8 = t & 1;
        int row = base + r;
        if (row < n) {
            float s[8];
            gather8<2>(reinterpret_cast<const uint4*>(p1), row, c8, s);
            float dv = g_dinv[row];
            #pragma unroll
            for (int j = 0; j < 8; j++) sV[r][c8 * 8 + j] = dv * s[j];
        }
    }
    __syncthreads();
    // phase B: TPR=32 (warp per 4-row group), 8 groups -> 32 rows/iter, 4 iters
    int grp = t >> 5, c4 = t & 31;
    #pragma unroll
    for (int it = 0; it < 4; it++) {
        int r0 = it * 32 + grp * 4;
        int row0 = base + r0;
        if (row0 >= n) continue;
        int rmax = n - row0;
        float4 acc[4];
        #pragma unroll
        for (int r = 0; r < 4; r++) acc[r] = make_float4(0.f, 0.f, 0.f, 0.f);
        #pragma unroll
        for (int k = 0; k < 16; k++) {
            float4 w = *reinterpret_cast<const float4*>(&sW[k * 128 + 4 * c4]);
            #pragma unroll
            for (int r = 0; r < 4; r++) {
                float xv = (r < rmax) ? sV[r0 + r][k] : 0.f;
                acc[r].x += xv * w.x; acc[r].y += xv * w.y;
                acc[r].z += xv * w.z; acc[r].w += xv * w.w;
            }
        }
        #pragma unroll
        for (int r = 0; r < 4; r++) {
            if (r < rmax) {
                int row = row0 + r;
                float dv = g_dinv[row];
                float4 b4 = *reinterpret_cast<const float4*>(&sB[4 * c4]);
                float o[4];
                o[0] = dv * tanhf(acc[r].x + b4.x);
                o[1] = dv * tanhf(acc[r].y + b4.y);
                o[2] = dv * tanhf(acc[r].z + b4.z);
                o[3] = dv * tanhf(acc[r].w + b4.w);
                __half2 h0 = __floats2half2_rn(o[0], o[1]);
                __half2 h1 = __floats2half2_rn(o[2], o[3]);
                uint2 u; u.x = *reinterpret_cast<unsigned*>(&h0);
                u.y = *reinterpret_cast<unsigned*>(&h1);
                *reinterpret_cast<uint2*>(outh + (size_t)row * 128 + 4 * c4) = u;
            }
        }
    }
}

// -------- L5 fused: v64 = dinv*(agg p4) in smem -> GEMM 64->64 -> tanh -> pool atomics --------
__global__ void __launch_bounds__(256) k_l5fused(const __half* __restrict__ p4in,
                                                 const float* __restrict__ W5,
                                                 const float* __restrict__ b5,
                                                 const int* __restrict__ batch, int n) {
    __shared__ float sV[64][64];
    __shared__ float sW[64 * 64];
    __shared__ float sB[64];
    int t = threadIdx.x;
    for (int i = t; i < 64 * 64; i += 256) sW[i] = W5[i];
    if (t < 64) sB[t] = b5[t];
    int base = blockIdx.x * 64;
    // phase A: 8 threads/row, 32 rows/pass, 2 passes
    #pragma unroll
    for (int pass = 0; pass < 2; pass++) {
        int r = pass * 32 + (t >> 3);
        int c8 = t & 7;
        int row = base + r;
        if (row < n) {
            float s[8];
            gather8<8>(reinterpret_cast<const uint4*>(p4in), row, c8, s);
            float dv = g_dinv[row];
            #pragma unroll
            for (int j = 0; j < 8; j++) sV[r][c8 * 8 + j] = dv * s[j];
        }
    }
    __syncthreads();
    // phase B: TPR=16, 16 groups x 4 rows = 64 rows
    int grp = t >> 4, c4 = t & 15;
    int row0 = base + grp * 4;
    if (row0 >= n) return;
    int rmax = n - row0;
    float4 acc[4];
    #pragma unroll
    for (int r = 0; r < 4; r++) acc[r] = make_float4(0.f, 0.f, 0.f, 0.f);
    #pragma unroll 8
    for (int k = 0; k < 64; k++) {
        float4 w = *reinterpret_cast<const float4*>(&sW[k * 64 + 4 * c4]);
        #pragma unroll
        for (int r = 0; r < 4; r++) {
            float xv = (r < rmax) ? sV[grp * 4 + r][k] : 0.f;
            acc[r].x += xv * w.x; acc[r].y += xv * w.y;
            acc[r].z += xv * w.z; acc[r].w += xv * w.w;
        }
    }
    #pragma unroll
    for (int r = 0; r < 4; r++) {
        if (r < rmax) {
            int row = row0 + r;
            float4 b4 = *reinterpret_cast<const float4*>(&sB[4 * c4]);
            float o0 = tanhf(acc[r].x + b4.x);
            float o1 = tanhf(acc[r].y + b4.y);
            float o2 = tanhf(acc[r].z + b4.z);
            float o3 = tanhf(acc[r].w + b4.w);
            int g = batch[row];
            float* dst = &g_pool[g * 64 + 4 * c4];
            atomicAdd(dst + 0, o0); atomicAdd(dst + 1, o1);
            atomicAdd(dst + 2, o2); atomicAdd(dst + 3, o3);
            if (c4 == 0) atomicAdd(&g_cnt[g], 1);
        }
    }
}

__global__ void k_final(const float* __restrict__ Wc, const float* __restrict__ bc,
                        float* __restrict__ out) {
    int warp = (blockIdx.x * blockDim.x + threadIdx.x) / 32;
    int lane = threadIdx.x & 31;
    if (warp >= 128) return;
    float c = fmaxf((float)g_cnt[warp], 1.f);
    float s = g_pool[warp * 64 + lane] * Wc[lane] + g_pool[warp * 64 + lane + 32] * Wc[lane + 32];
    #pragma unroll
    for (int off = 16; off; off >>= 1) s += __shfl_down_sync(0xffffffffu, s, off);
    if (lane == 0) out[warp] = s / c + bc[0];
}

// -------- host side --------
static float* symA() { static float* p = nullptr; if (!p) cudaGetSymbolAddress((void**)&p, g_bufA); return p; }
static float* symB() { static float* p = nullptr; if (!p) cudaGetSymbolAddress((void**)&p, g_bufB); return p; }

extern "C" void kernel_launch(void* const* d_in, const int* in_sizes, int n_in,
                              void* d_out, int out_size) {
    const float* x     = (const float*)d_in[0];
    const int*   ei    = (const int*)d_in[1];     // int32 (JAX x64 disabled)
    const int*   batch = (const int*)d_in[2];     // int32
    const float* W1 = (const float*)d_in[3];  const float* b1 = (const float*)d_in[4];
    const float* W2 = (const float*)d_in[5];  const float* b2 = (const float*)d_in[6];
    const float* W3 = (const float*)d_in[7];  const float* b3 = (const float*)d_in[8];
    const float* W4 = (const float*)d_in[9];  const float* b4 = (const float*)d_in[10];
    const float* W5 = (const float*)d_in[11]; const float* b5 = (const float*)d_in[12];
    const float* Wc = (const float*)d_in[13]; const float* bc = (const float*)d_in[14];
    float* out = (float*)d_out;

    const int n = in_sizes[0] / 64;
    const int E = in_sizes[1] / 2;
    const int NB = (n + 255) / 256;

    __half* Ah = (__half*)symA();
    __half* Bh = (__half*)symB();

    // opt-in for 64KB+ dynamic smem on the 128x128 GEMM
    static bool attr_done = []() {
        cudaFuncSetAttribute((const void*)k_gemm<128,128,false,false,true,true>,
                             cudaFuncAttributeMaxDynamicSharedMemorySize,
                             (128 * 128 + 128) * 4);
        return true;
    }();
    (void)attr_done;

    // ---- CSR build ----
    k_init<<<512, 256>>>(n);
    k_count<<<(E + 255) / 256, 256>>>(ei, E);
    k_scan1<<<NB, 256>>>(n);
    k_scan2<<<1, 512>>>(NB);
    k_scan3<<<NB, 256>>>(n, E);
    k_fill<<<(E + 255) / 256, 256>>>(ei, E);

    auto ablocks = [&](int F) { return (n * (F / 8) + 255) / 256; };
    auto gemmblk = [&](int Fo) { int rpb = 4096 / Fo; return (n + rpb - 1) / rpb; };

    // L1: 64->16 transform-first: Ah = fp16(dinv * (x @ W1))
    k_gemm<64,16,false,true,true,false><<<gemmblk(16), 256, (64*16+16)*4>>>(x, W1, nullptr, Ah, n);
    k_agg1<16><<<ablocks(16), 256>>>(Ah, b1, Bh, n);                 // Bh = p1

    // L2 fused: agg(p1) -> GEMM 16->128 -> tanh,dinv -> Ah = p2 (fp16)
    k_l2fused<<<(n + 127) / 128, 256>>>(Bh, W2, b2, Ah, n);

    // L3: 128->128 transform-first (fp16 in/out)
    k_gemm<128,128,false,false,true,true><<<gemmblk(128), 256, (128*128+128)*4>>>(Ah, W3, nullptr, Bh, n);
    k_agg1<128><<<ablocks(128), 256>>>(Bh, b3, Ah, n);               // Ah = p3

    // L4: 128->64 transform-first (fp16 in/out)
    k_gemm<128,64,false,false,true,true><<<gemmblk(64), 256, (128*64+64)*4>>>(Ah, W4, nullptr, Bh, n);
    k_agg1<64><<<ablocks(64), 256>>>(Bh, b4, Ah, n);                 // Ah = p4

    // L5 fused: agg(p4) -> GEMM 64->64 -> tanh -> pool atomics
    k_l5fused<<<(n + 63) / 64, 256>>>(Ah, W5, b5, batch, n);

    // ---- head ----
    k_final<<<32, 128>>>(Wc, bc, out);
    (void)out_size; (void)n_in;
}

// round 8
// speedup vs baseline: 1.7736x; 1.2840x over previous
#include <cuda_runtime.h>
#include <cuda_fp16.h>
#include <cstdint>
#include <math.h>

#define MAX_N 100000
#define MAX_E 1600000

// -------- scratch (static device globals; allocation-free) --------
static __device__ float g_bufA[(size_t)MAX_N * 128];
static __device__ float g_bufB[(size_t)MAX_N * 128];
static __device__ float g_dinv[MAX_N];
static __device__ int   g_indeg[MAX_N];
static __device__ int   g_cursor[MAX_N];
static __device__ int   g_offsets[MAX_N + 1];
static __device__ int   g_partials[1024];
static __device__ int   g_csr[MAX_E];
static __device__ float g_pool[128 * 64];
static __device__ int   g_cnt[128];
static __device__ __half g_W3h[128 * 136];   // Wt3[n][k], stride 136
static __device__ __half g_W4h[64 * 136];    // Wt4[n][k], stride 136

// -------- fp16 helpers --------
__device__ __forceinline__ void acc8(float* a, uint4 v) {
    __half2 h0 = *reinterpret_cast<__half2*>(&v.x);
    __half2 h1 = *reinterpret_cast<__half2*>(&v.y);
    __half2 h2 = *reinterpret_cast<__half2*>(&v.z);
    __half2 h3 = *reinterpret_cast<__half2*>(&v.w);
    float2 f0 = __half22float2(h0); a[0] += f0.x; a[1] += f0.y;
    float2 f1 = __half22float2(h1); a[2] += f1.x; a[3] += f1.y;
    float2 f2 = __half22float2(h2); a[4] += f2.x; a[5] += f2.y;
    float2 f3 = __half22float2(h3); a[6] += f3.x; a[7] += f3.y;
}

__device__ __forceinline__ uint4 pack8(const float* a) {
    __half2 h0 = __floats2half2_rn(a[0], a[1]);
    __half2 h1 = __floats2half2_rn(a[2], a[3]);
    __half2 h2 = __floats2half2_rn(a[4], a[5]);
    __half2 h3 = __floats2half2_rn(a[6], a[7]);
    uint4 r;
    r.x = *reinterpret_cast<unsigned*>(&h0);
    r.y = *reinterpret_cast<unsigned*>(&h1);
    r.z = *reinterpret_cast<unsigned*>(&h2);
    r.w = *reinterpret_cast<unsigned*>(&h3);
    return r;
}

// gather 8 features (uint4 of fp16) for node d, lane-chunk c8; o = self + sum(neighbors)
template<int TPN>
__device__ __forceinline__ void gather8(const uint4* __restrict__ p4, int d, int c8, float* o) {
    float a0[8], a1[8];
    #pragma unroll
    for (int j = 0; j < 8; j++) { a0[j] = 0.f; a1[j] = 0.f; }
    acc8(a0, p4[(size_t)d * TPN + c8]);  // self loop
    const int s0 = g_offsets[d], s1 = g_offsets[d + 1];
    int e = s0;
    for (; e + 4 <= s1; e += 4) {
        int i0 = g_csr[e], i1 = g_csr[e + 1], i2 = g_csr[e + 2], i3 = g_csr[e + 3];
        uint4 v0 = __ldg(&p4[(size_t)i0 * TPN + c8]);
        uint4 v1 = __ldg(&p4[(size_t)i1 * TPN + c8]);
        uint4 v2 = __ldg(&p4[(size_t)i2 * TPN + c8]);
        uint4 v3 = __ldg(&p4[(size_t)i3 * TPN + c8]);
        acc8(a0, v0); acc8(a1, v1); acc8(a0, v2); acc8(a1, v3);
    }
    for (; e < s1; e++) {
        uint4 v = __ldg(&p4[(size_t)g_csr[e] * TPN + c8]);
        acc8(a0, v);
    }
    #pragma unroll
    for (int j = 0; j < 8; j++) o[j] = a0[j] + a1[j];
}

// -------- init / CSR build --------
__global__ void k_init(int n) {
    int stride = gridDim.x * blockDim.x;
    int i = blockIdx.x * blockDim.x + threadIdx.x;
    for (int j = i; j < n; j += stride) { g_indeg[j] = 0; g_cursor[j] = 0; }
    for (int j = i; j < 128 * 64; j += stride) g_pool[j] = 0.f;
    if (i < 128) g_cnt[i] = 0;
}

__global__ void k_count(const int* __restrict__ ei, int E) {
    int stride = gridDim.x * blockDim.x;
    for (int e = blockIdx.x * blockDim.x + threadIdx.x; e < E; e += stride) {
        int d = ei[E + e];
        atomicAdd(&g_indeg[d], 1);
    }
}

__global__ void k_scan1(int n) {
    __shared__ int s[256];
    int t = threadIdx.x;
    int idx = blockIdx.x * 256 + t;
    int v = (idx < n) ? g_indeg[idx] : 0;
    if (idx < n) g_dinv[idx] = rsqrtf((float)(v + 1));  // +1 self loop
    s[t] = v;
    __syncthreads();
    #pragma unroll
    for (int off = 1; off < 256; off <<= 1) {
        int add = (t >= off) ? s[t - off] : 0;
        __syncthreads();
        s[t] += add;
        __syncthreads();
    }
    if (idx < n) g_offsets[idx] = s[t] - v;
    if (t == 255) g_partials[blockIdx.x] = s[255];
}

__global__ void k_scan2(int nb) {
    __shared__ int s[512];
    int t = threadIdx.x;
    int v = (t < nb) ? g_partials[t] : 0;
    s[t] = v;
    __syncthreads();
    #pragma unroll
    for (int off = 1; off < 512; off <<= 1) {
        int add = (t >= off) ? s[t - off] : 0;
        __syncthreads();
        s[t] += add;
        __syncthreads();
    }
    if (t < nb) g_partials[t] = s[t] - v;
}

__global__ void k_scan3(int n, int E) {
    int idx = blockIdx.x * 256 + threadIdx.x;
    if (idx < n) g_offsets[idx] += g_partials[blockIdx.x];
    if (idx == 0) g_offsets[n] = E;
}

__global__ void k_fill(const int* __restrict__ ei, int E) {
    int stride = gridDim.x * blockDim.x;
    for (int e = blockIdx.x * blockDim.x + threadIdx.x; e < E; e += stride) {
        int s = ei[e];
        int d = ei[E + e];
        int pos = g_offsets[d] + atomicAdd(&g_cursor[d], 1);
        g_csr[pos] = s;
    }
}

// -------- weight convert: W[k][n] fp32 -> Wt[n][k] fp16 (stride Fi+8) --------
__global__ void k_wconv(const float* __restrict__ W, __half* __restrict__ Wt, int Fi, int Fo) {
    int i = blockIdx.x * 256 + threadIdx.x;
    if (i < Fi * Fo) {
        int k = i / Fo, nn = i % Fo;
        Wt[nn * (Fi + 8) + k] = __float2half(W[i]);
    }
}

// -------- HMMA GEMM (no epilogue): out = in @ W, fp16 in/out, fp32 accum --------
// in: [n][Fi] fp16 row-major; Wt: [Fo][Fi+8] fp16 (W transposed); out: [n][Fo] fp16
template<int Fi, int Fo>
__global__ void __launch_bounds__(256) k_hmma(const __half* __restrict__ in,
                                              const __half* __restrict__ Wt,
                                              __half* __restrict__ outh, int n) {
    constexpr int AS = Fi + 8;     // fp16 stride (136): ldmatrix + B-LDS conflict-free
    extern __shared__ __half sm[];
    __half* sA = sm;               // [128][AS]
    __half* sW = sm + 128 * AS;    // [Fo][AS]
    const int t = threadIdx.x;
    const int base = blockIdx.x * 128;

    // load Wt (L2-cached)
    for (int i = t; i < Fo * AS / 8; i += 256)
        reinterpret_cast<uint4*>(sW)[i] = reinterpret_cast<const uint4*>(Wt)[i];
    // load A tile (zero-pad rows >= n)
    constexpr int RU = Fi / 8;     // uint4 per row
    for (int i = t; i < 128 * RU; i += 256) {
        int r = i / RU, c = i % RU;
        uint4 v = (base + r < n)
            ? __ldg(reinterpret_cast<const uint4*>(in + (size_t)(base + r) * Fi) + c)
            : make_uint4(0u, 0u, 0u, 0u);
        reinterpret_cast<uint4*>(sA + r * AS)[c] = v;
    }
    __syncthreads();

    const int w = t >> 5, lane = t & 31;
    const int m0 = w * 16;                       // warp's 16-row slice
    constexpr int NT = Fo / 8;                   // n-tiles
    float c[NT][4];
    #pragma unroll
    for (int j = 0; j < NT; j++) {
        c[j][0] = 0.f; c[j][1] = 0.f; c[j][2] = 0.f; c[j][3] = 0.f;
    }

    // ldmatrix lane address (canonical m16k16 recipe)
    const int mm = lane >> 3;
    const int arow = m0 + (lane & 7) + 8 * (mm & 1);
    const int acol0 = 8 * (mm >> 1);

    #pragma unroll
    for (int k0 = 0; k0 < Fi; k0 += 16) {
        uint32_t a0, a1, a2, a3;
        uint32_t saddr = (uint32_t)__cvta_generic_to_shared(sA + arow * AS + acol0 + k0);
        asm volatile("ldmatrix.sync.aligned.m8n8.x4.shared.b16 {%0,%1,%2,%3}, [%4];"
                     : "=r"(a0), "=r"(a1), "=r"(a2), "=r"(a3) : "r"(saddr));
        const __half* bp = sW + (lane >> 2) * AS + k0 + (lane & 3) * 2;
        #pragma unroll
        for (int j = 0; j < NT; j++) {
            uint32_t b0 = *reinterpret_cast<const uint32_t*>(bp + j * 8 * AS);
            uint32_t b1 = *reinterpret_cast<const uint32_t*>(bp + j * 8 * AS + 8);
            asm volatile(
                "mma.sync.aligned.m16n8k16.row.col.f32.f16.f16.f32 "
                "{%0,%1,%2,%3}, {%4,%5,%6,%7}, {%8,%9}, {%0,%1,%2,%3};"
                : "+f"(c[j][0]), "+f"(c[j][1]), "+f"(c[j][2]), "+f"(c[j][3])
                : "r"(a0), "r"(a1), "r"(a2), "r"(a3), "r"(b0), "r"(b1));
        }
    }

    // store: d0,d1 -> row lane/4, cols (lane%4)*2..+1 ; d2,d3 -> row+8
    const int r0 = base + m0 + (lane >> 2);
    const int col = (lane & 3) * 2;
    #pragma unroll
    for (int j = 0; j < NT; j++) {
        if (r0 < n) {
            __half2 h = __floats2half2_rn(c[j][0], c[j][1]);
            *reinterpret_cast<__half2*>(outh + (size_t)r0 * Fo + j * 8 + col) = h;
        }
        if (r0 + 8 < n) {
            __half2 h = __floats2half2_rn(c[j][2], c[j][3]);
            *reinterpret_cast<__half2*>(outh + (size_t)(r0 + 8) * Fo + j * 8 + col) = h;
        }
    }
}

// -------- scalar fused GEMM (L1 only): out = epi(in @ W); fp32 in, fp16 out --------
template<int Fi, int Fo, bool SCALE>
__global__ void __launch_bounds__(256) k_gemm(const float* __restrict__ in,
                                              const float* __restrict__ W,
                                              __half* __restrict__ outh, int n) {
    extern __shared__ float sWf[];
    for (int i = threadIdx.x; i < Fi * Fo; i += 256) sWf[i] = W[i];
    __syncthreads();

    constexpr int TPR = Fo / 4;
    constexpr int GRP = 256 / TPR;
    const int grp = threadIdx.x / TPR;
    const int c4  = threadIdx.x % TPR;
    constexpr int RPB = GRP * 4;

    for (int row0 = blockIdx.x * RPB + grp * 4; row0 < n; row0 += gridDim.x * RPB) {
        float4 acc[4];
        #pragma unroll
        for (int r = 0; r < 4; r++) acc[r] = make_float4(0.f, 0.f, 0.f, 0.f);
        const int rmax = n - row0;

        #pragma unroll 4
        for (int k = 0; k < Fi; k += 4) {
            float4 xr[4];
            #pragma unroll
            for (int r = 0; r < 4; r++)
                xr[r] = (r < rmax)
                    ? *reinterpret_cast<const float4*>(&in[(size_t)(row0 + r) * Fi + k])
                    : make_float4(0.f, 0.f, 0.f, 0.f);
            #pragma unroll
            for (int kk = 0; kk < 4; kk++) {
                float4 w = *reinterpret_cast<const float4*>(&sWf[(k + kk) * Fo + 4 * c4]);
                #pragma unroll
                for (int r = 0; r < 4; r++) {
                    float xv = (kk == 0) ? xr[r].x : (kk == 1) ? xr[r].y : (kk == 2) ? xr[r].z : xr[r].w;
                    acc[r].x += xv * w.x; acc[r].y += xv * w.y;
                    acc[r].z += xv * w.z; acc[r].w += xv * w.w;
                }
            }
        }
        #pragma unroll
        for (int r = 0; r < 4; r++) {
            if (r < rmax) {
                int row = row0 + r;
                float4 a = acc[r];
                if (SCALE) {
                    float dv = g_dinv[row];
                    a.x *= dv; a.y *= dv; a.z *= dv; a.w *= dv;
                }
                __half2 h0 = __floats2half2_rn(a.x, a.y);
                __half2 h1 = __floats2half2_rn(a.z, a.w);
                uint2 u; u.x = *reinterpret_cast<unsigned*>(&h0);
                u.y = *reinterpret_cast<unsigned*>(&h1);
                *reinterpret_cast<uint2*>(outh + (size_t)row * Fo + 4 * c4) = u;
            }
        }
    }
}

// -------- standalone aggregation (post-GEMM): out = dinv*tanh(dinv*agg+b), fp16 out --------
template<int F>
__global__ void __launch_bounds__(256) k_agg1(const __half* __restrict__ p,
                                              const float* __restrict__ bias,
                                              __half* __restrict__ outh, int n) {
    constexpr int TPN = F / 8;
    int t = blockIdx.x * 256 + threadIdx.x;
    int d = t / TPN;
    int c8 = t % TPN;
    if (d >= n) return;
    float s[8];
    gather8<TPN>(reinterpret_cast<const uint4*>(p), d, c8, s);
    float dv = g_dinv[d];
    const float* b = &bias[c8 * 8];
    float o[8];
    #pragma unroll
    for (int j = 0; j < 8; j++) o[j] = dv * tanhf(dv * s[j] + b[j]);
    *reinterpret_cast<uint4*>(outh + (size_t)d * F + c8 * 8) = pack8(o);
}

// -------- L2 fused: v16 = dinv*(agg p1) -> GEMM 16->128 -> tanh,dinv -> fp16 --------
__global__ void __launch_bounds__(256) k_l2fused(const __half* __restrict__ p1,
                                                 const float* __restrict__ W2,
                                                 const float* __restrict__ b2,
                                                 __half* __restrict__ outh, int n) {
    __shared__ float sV[128][16];
    __shared__ float sW[16 * 128];
    __shared__ float sB[128];
    int t = threadIdx.x;
    for (int i = t; i < 16 * 128; i += 256) sW[i] = W2[i];
    if (t < 128) sB[t] = b2[t];
    int base = blockIdx.x * 128;
    {
        int r = t >> 1, c8 = t & 1;
        int row = base + r;
        if (row < n) {
            float s[8];
            gather8<2>(reinterpret_cast<const uint4*>(p1), row, c8, s);
            float dv = g_dinv[row];
            #pragma unroll
            for (int j = 0; j < 8; j++) sV[r][c8 * 8 + j] = dv * s[j];
        }
    }
    __syncthreads();
    int grp = t >> 5, c4 = t & 31;
    #pragma unroll
    for (int it = 0; it < 4; it++) {
        int r0 = it * 32 + grp * 4;
        int row0 = base + r0;
        if (row0 >= n) continue;
        int rmax = n - row0;
        float4 acc[4];
        #pragma unroll
        for (int r = 0; r < 4; r++) acc[r] = make_float4(0.f, 0.f, 0.f, 0.f);
        #pragma unroll
        for (int k = 0; k < 16; k++) {
            float4 w = *reinterpret_cast<const float4*>(&sW[k * 128 + 4 * c4]);
            #pragma unroll
            for (int r = 0; r < 4; r++) {
                float xv = (r < rmax) ? sV[r0 + r][k] : 0.f;
                acc[r].x += xv * w.x; acc[r].y += xv * w.y;
                acc[r].z += xv * w.z; acc[r].w += xv * w.w;
            }
        }
        #pragma unroll
        for (int r = 0; r < 4; r++) {
            if (r < rmax) {
                int row = row0 + r;
                float dv = g_dinv[row];
                float4 b4 = *reinterpret_cast<const float4*>(&sB[4 * c4]);
                float o0 = dv * tanhf(acc[r].x + b4.x);
                float o1 = dv * tanhf(acc[r].y + b4.y);
                float o2 = dv * tanhf(acc[r].z + b4.z);
                float o3 = dv * tanhf(acc[r].w + b4.w);
                __half2 h0 = __floats2half2_rn(o0, o1);
                __half2 h1 = __floats2half2_rn(o2, o3);
                uint2 u; u.x = *reinterpret_cast<unsigned*>(&h0);
                u.y = *reinterpret_cast<unsigned*>(&h1);
                *reinterpret_cast<uint2*>(outh + (size_t)row * 128 + 4 * c4) = u;
            }
        }
    }
}

// -------- L5 fused: v64 = dinv*(agg p4) -> GEMM 64->64 -> tanh -> pool atomics --------
__global__ void __launch_bounds__(256) k_l5fused(const __half* __restrict__ p4in,
                                                 const float* __restrict__ W5,
                                                 const float* __restrict__ b5,
                                                 const int* __restrict__ batch, int n) {
    __shared__ float sV[64][64];
    __shared__ float sW[64 * 64];
    __shared__ float sB[64];
    int t = threadIdx.x;
    for (int i = t; i < 64 * 64; i += 256) sW[i] = W5[i];
    if (t < 64) sB[t] = b5[t];
    int base = blockIdx.x * 64;
    #pragma unroll
    for (int pass = 0; pass < 2; pass++) {
        int r = pass * 32 + (t >> 3);
        int c8 = t & 7;
        int row = base + r;
        if (row < n) {
            float s[8];
            gather8<8>(reinterpret_cast<const uint4*>(p4in), row, c8, s);
            float dv = g_dinv[row];
            #pragma unroll
            for (int j = 0; j < 8; j++) sV[r][c8 * 8 + j] = dv * s[j];
        }
    }
    __syncthreads();
    int grp = t >> 4, c4 = t & 15;
    int row0 = base + grp * 4;
    if (row0 >= n) return;
    int rmax = n - row0;
    float4 acc[4];
    #pragma unroll
    for (int r = 0; r < 4; r++) acc[r] = make_float4(0.f, 0.f, 0.f, 0.f);
    #pragma unroll 8
    for (int k = 0; k < 64; k++) {
        float4 w = *reinterpret_cast<const float4*>(&sW[k * 64 + 4 * c4]);
        #pragma unroll
        for (int r = 0; r < 4; r++) {
            float xv = (r < rmax) ? sV[grp * 4 + r][k] : 0.f;
            acc[r].x += xv * w.x; acc[r].y += xv * w.y;
            acc[r].z += xv * w.z; acc[r].w += xv * w.w;
        }
    }
    #pragma unroll
    for (int r = 0; r < 4; r++) {
        if (r < rmax) {
            int row = row0 + r;
            float4 b4 = *reinterpret_cast<const float4*>(&sB[4 * c4]);
            float o0 = tanhf(acc[r].x + b4.x);
            float o1 = tanhf(acc[r].y + b4.y);
            float o2 = tanhf(acc[r].z + b4.z);
            float o3 = tanhf(acc[r].w + b4.w);
            int g = batch[row];
            float* dst = &g_pool[g * 64 + 4 * c4];
            atomicAdd(dst + 0, o0); atomicAdd(dst + 1, o1);
            atomicAdd(dst + 2, o2); atomicAdd(dst + 3, o3);
            if (c4 == 0) atomicAdd(&g_cnt[g], 1);
        }
    }
}

__global__ void k_final(const float* __restrict__ Wc, const float* __restrict__ bc,
                        float* __restrict__ out) {
    int warp = (blockIdx.x * blockDim.x + threadIdx.x) / 32;
    int lane = threadIdx.x & 31;
    if (warp >= 128) return;
    float c = fmaxf((float)g_cnt[warp], 1.f);
    float s = g_pool[warp * 64 + lane] * Wc[lane] + g_pool[warp * 64 + lane + 32] * Wc[lane + 32];
    #pragma unroll
    for (int off = 16; off; off >>= 1) s += __shfl_down_sync(0xffffffffu, s, off);
    if (lane == 0) out[warp] = s / c + bc[0];
}

// -------- host side --------
static float* symA() { static float* p = nullptr; if (!p) cudaGetSymbolAddress((void**)&p, g_bufA); return p; }
static float* symB() { static float* p = nullptr; if (!p) cudaGetSymbolAddress((void**)&p, g_bufB); return p; }
static __half* symW3() { static __half* p = nullptr; if (!p) cudaGetSymbolAddress((void**)&p, g_W3h); return p; }
static __half* symW4() { static __half* p = nullptr; if (!p) cudaGetSymbolAddress((void**)&p, g_W4h); return p; }

extern "C" void kernel_launch(void* const* d_in, const int* in_sizes, int n_in,
                              void* d_out, int out_size) {
    const float* x     = (const float*)d_in[0];
    const int*   ei    = (const int*)d_in[1];     // int32 (JAX x64 disabled)
    const int*   batch = (const int*)d_in[2];     // int32
    const float* W1 = (const float*)d_in[3];  const float* b1 = (const float*)d_in[4];
    const float* W2 = (const float*)d_in[5];  const float* b2 = (const float*)d_in[6];
    const float* W3 = (const float*)d_in[7];  const float* b3 = (const float*)d_in[8];
    const float* W4 = (const float*)d_in[9];  const float* b4 = (const float*)d_in[10];
    const float* W5 = (const float*)d_in[11]; const float* b5 = (const float*)d_in[12];
    const float* Wc = (const float*)d_in[13]; const float* bc = (const float*)d_in[14];
    float* out = (float*)d_out;

    const int n = in_sizes[0] / 64;
    const int E = in_sizes[1] / 2;
    const int NB = (n + 255) / 256;

    __half* Ah = (__half*)symA();
    __half* Bh = (__half*)symB();

    constexpr int SM3 = (128 + 128) * 136 * 2;   // 69632 B
    constexpr int SM4 = (128 + 64) * 136 * 2;    // 52224 B
    static bool attr_done = []() {
        cudaFuncSetAttribute((const void*)k_hmma<128, 128>,
                             cudaFuncAttributeMaxDynamicSharedMemorySize, SM3);
        cudaFuncSetAttribute((const void*)k_hmma<128, 64>,
                             cudaFuncAttributeMaxDynamicSharedMemorySize, SM4);
        return true;
    }();
    (void)attr_done;

    // ---- CSR build + weight conversion ----
    k_init<<<512, 256>>>(n);
    k_count<<<(E + 255) / 256, 256>>>(ei, E);
    k_wconv<<<(128 * 128 + 255) / 256, 256>>>(W3, symW3(), 128, 128);
    k_wconv<<<(128 * 64 + 255) / 256, 256>>>(W4, symW4(), 128, 64);
    k_scan1<<<NB, 256>>>(n);
    k_scan2<<<1, 512>>>(NB);
    k_scan3<<<NB, 256>>>(n, E);
    k_fill<<<(E + 255) / 256, 256>>>(ei, E);

    auto ablocks = [&](int F) { return (n * (F / 8) + 255) / 256; };

    // L1: 64->16 scalar transform-first: Ah = fp16(dinv * (x @ W1))
    k_gemm<64, 16, true><<<(n + 255) / 256, 256, 64 * 16 * 4>>>(x, W1, Ah, n);
    k_agg1<16><<<ablocks(16), 256>>>(Ah, b1, Bh, n);                 // Bh = p1

    // L2 fused: agg(p1) -> GEMM 16->128 -> tanh,dinv -> Ah = p2
    k_l2fused<<<(n + 127) / 128, 256>>>(Bh, W2, b2, Ah, n);

    // L3: 128->128 HMMA (no epilogue), then agg
    k_hmma<128, 128><<<(n + 127) / 128, 256, SM3>>>(Ah, symW3(), Bh, n);
    k_agg1<128><<<ablocks(128), 256>>>(Bh, b3, Ah, n);               // Ah = p3

    // L4: 128->64 HMMA, then agg
    k_hmma<128, 64><<<(n + 127) / 128, 256, SM4>>>(Ah, symW4(), Bh, n);
    k_agg1<64><<<ablocks(64), 256>>>(Bh, b4, Ah, n);                 // Ah = p4

    // L5 fused: agg(p4) -> GEMM 64->64 -> tanh -> pool atomics
    k_l5fused<<<(n + 63) / 64, 256>>>(Ah, W5, b5, batch, n);

    // ---- head ----
    k_final<<<32, 128>>>(Wc, bc, out);
    (void)out_size; (void)n_in;
}